// round 8
// baseline (speedup 1.0000x reference)
#include <cuda_runtime.h>
#include <cuda_fp16.h>
#include <math.h>
#include <stdint.h>

#define NN 100000
#define NE 1600000
#define DIM 128

// ---------------- scratch (static device globals; no allocation) -------------
__device__ int    g_count[NN];                  // in-degree histogram
__device__ int    g_off[NN + 1];                // CSR offsets
__device__ int    g_cur[NN];                    // scatter cursors
__device__ int2   g_edge[NE];                   // packed (src, exp-bits) sorted by dst
__device__ __half g_hvh[(size_t)NN * DIM];      // projected node feats (fp16)
__device__ float  g_ctx[(size_t)NN * DIM];      // aggregated context (fp32)
__device__ __half g_h[(size_t)NN * DIM];        // hidden layer (fp16)
// scan scratch
__device__ int    g_excl[NN];
__device__ int    g_bsum[128];
__device__ int    g_bpre[128];

// ---------------- small kernels ---------------------------------------------
__global__ void init_kernel() {
    int i = blockIdx.x * blockDim.x + threadIdx.x;
    if (i < NN) g_count[i] = 0;
}

// count-only pass (z is accumulated inside the aggregate now)
__global__ void count_pass(const int* __restrict__ dst) {
    int i = blockIdx.x * blockDim.x + threadIdx.x;
    if (i < NE) atomicAdd(&g_count[dst[i]], 1);
}

// ---------------- 3-phase parallel scan of g_count -> g_off ------------------
__global__ void scan_phase_a() {
    __shared__ int sh[1024];
    int t = threadIdx.x;
    int b = blockIdx.x;
    int i = b * 1024 + t;
    int c = (i < NN) ? g_count[i] : 0;
    sh[t] = c;
    __syncthreads();
#pragma unroll
    for (int off = 1; off < 1024; off <<= 1) {
        int v = sh[t] + ((t >= off) ? sh[t - off] : 0);
        __syncthreads();
        sh[t] = v;
        __syncthreads();
    }
    if (i < NN) g_excl[i] = sh[t] - c;
    if (t == 1023) g_bsum[b] = sh[1023];
}

__global__ void scan_phase_b(int nb) {
    __shared__ int sh[128];
    int t = threadIdx.x;
    int v0 = (t < nb) ? g_bsum[t] : 0;
    sh[t] = v0;
    __syncthreads();
#pragma unroll
    for (int off = 1; off < 128; off <<= 1) {
        int v = sh[t] + ((t >= off) ? sh[t - off] : 0);
        __syncthreads();
        sh[t] = v;
        __syncthreads();
    }
    if (t < nb) g_bpre[t] = sh[t] - v0;
    if (t == nb - 1) g_off[NN] = sh[t];
}

__global__ void scan_phase_c() {
    int i = blockIdx.x * blockDim.x + threadIdx.x;
    if (i < NN) {
        int o = g_bpre[i >> 10] + g_excl[i];
        g_off[i] = o;
        g_cur[i] = o;
    }
}

// scatter (src, unnormalized e=exp(logit)) into CSR order.
// (no max-shift needed: logits ~ N(0,1); exp cannot overflow and the
//  normalized ratio e/z is shift-invariant up to fp32 rounding)
__global__ void edge_scatter(const float* __restrict__ logits,
                             const int* __restrict__ src,
                             const int* __restrict__ dst) {
    int i = blockIdx.x * blockDim.x + threadIdx.x;
    if (i < NE) {
        int d = dst[i];
        int pos = atomicAdd(&g_cur[d], 1);
        float e = expf(logits[i]);
        g_edge[pos] = make_int2(src[i], __float_as_int(e));
    }
}

// warp per destination node: ctx[v] = elu( (sum_e e_uv * hv[u]) / (sum_e e_uv) )
// hv fp16, fp32 accumulate; z accumulated in-loop (lane-redundant, free).
__global__ void aggregate_kernel(const __half2* __restrict__ hv2,
                                 float* __restrict__ ctx) {
    int gw   = (blockIdx.x * blockDim.x + threadIdx.x) >> 5;
    int lane = threadIdx.x & 31;
    if (gw >= NN) return;
    int s = g_off[gw];
    int e = g_off[gw + 1];
    float4 acc = make_float4(0.f, 0.f, 0.f, 0.f);
    float az = 0.f;
    for (int i = s; i < e; i++) {
        int2  ed = g_edge[i];
        float a  = __int_as_float(ed.y);
        az += a;
        const __half2* row = hv2 + (size_t)ed.x * (DIM / 2) + lane * 2;
        uint2 u = *(const uint2*)row;
        __half2 h0 = *(__half2*)&u.x;
        __half2 h1 = *(__half2*)&u.y;
        float2 f0 = __half22float2(h0);
        float2 f1 = __half22float2(h1);
        acc.x = fmaf(a, f0.x, acc.x);
        acc.y = fmaf(a, f0.y, acc.y);
        acc.z = fmaf(a, f1.x, acc.z);
        acc.w = fmaf(a, f1.y, acc.w);
    }
    if (e > s) {
        float invz = 1.0f / az;
        acc.x *= invz; acc.y *= invz; acc.z *= invz; acc.w *= invz;
    }
    acc.x = acc.x > 0.f ? acc.x : expm1f(acc.x);
    acc.y = acc.y > 0.f ? acc.y : expm1f(acc.y);
    acc.z = acc.z > 0.f ? acc.z : expm1f(acc.z);
    acc.w = acc.w > 0.f ? acc.w : expm1f(acc.w);
    *(float4*)(ctx + (size_t)gw * DIM + lane * 4) = acc;
}

// ---------------- fp16 tensor-core GEMM (A-prefetch pipelined) ---------------
// C[M,128] = act( A1[:,0:128] @ B[0:128,:] (+ A2[:,0:128] @ B[128:256,:]) + bias )
// mma.sync.aligned.m16n8k16.row.col.f32.f16.f16.f32; fp32 accumulate.
// 128x128 block tile, 8 warps (2x4), warp tile 64x32, BK=32 (2 k16 steps).
// A staged as half2 [row][16], row stride 20 half2:
//   a-frag word idx = row*20 + t4(+4); g4*20 mod 32 = {0,20,8,28,16,4,24,12}
//   -> the 8 g4-ranges of 4 banks are disjoint -> conflict-free.
// B staged as half [k][col], row stride 136 halves (272B, 8B-aligned):
//   b-frag word idx = 68*k + col/2, k=2*t4 -> t4 offsets {0,8,16,24} mod 32,
//   g4 pairs share a word (broadcast) -> conflict-free.

__global__ void __launch_bounds__(256, 2)
gemm_f16(const void* __restrict__ A1v, const void* __restrict__ A2v,
         const float* __restrict__ B, const float* __restrict__ bias,
         float* __restrict__ C, __half* __restrict__ Ch,
         int M, int K, int do_relu, int a_half) {
    __shared__ __half2 As[128 * 20];
    __shared__ __half  Bs[32 * 136];

    const int tid  = threadIdx.x;
    const int lane = tid & 31;
    const int wid  = tid >> 5;
    const int wm   = wid >> 2;        // 0..1  -> warp rows base wm*64
    const int wn   = wid & 3;         // 0..3  -> warp cols base wn*32
    const int m0   = blockIdx.x * 128;
    const int g4   = lane >> 2;       // groupID
    const int t4   = lane & 3;        // thread-in-group

    const float*  A1f = (const float*)A1v;
    const float*  A2f = (const float*)A2v;
    const __half* A1h = (const __half*)A1v;

    float acc[4][4][4];
#pragma unroll
    for (int mt = 0; mt < 4; mt++)
#pragma unroll
        for (int nt = 0; nt < 4; nt++)
#pragma unroll
            for (int r = 0; r < 4; r++) acc[mt][nt][r] = 0.f;

    // register prefetch buffers: fp32 path uses f4[4]; fp16 path uses u2[4]
    float4 f4[4];
    uint2  u2[4];

    // ---- tile load helpers (macro-free, inlined by unrolled loops) ----
    auto load_a = [&](int k0) {
#pragma unroll
        for (int j = 0; j < 4; j++) {
            int f   = tid + j * 256;    // 0..1023
            int row = f >> 3;           // 0..127
            int seg = f & 7;            // 0..7 (4 halves / 4 floats each)
            int g   = m0 + row;
            int kc  = k0 + seg * 4;
            if (a_half) {
                uint2 v = make_uint2(0u, 0u);
                if (g < M) v = *(const uint2*)(A1h + (size_t)g * 128 + kc);
                u2[j] = v;
            } else {
                const float* Ap = A1f;
                if (kc >= 128) { Ap = A2f; kc -= 128; }
                float4 v = make_float4(0.f, 0.f, 0.f, 0.f);
                if (g < M) v = *(const float4*)(Ap + (size_t)g * 128 + kc);
                f4[j] = v;
            }
        }
    };
    auto store_a = [&]() {
#pragma unroll
        for (int j = 0; j < 4; j++) {
            int f   = tid + j * 256;
            int row = f >> 3;
            int seg = f & 7;
            __half2 h0, h1;
            if (a_half) {
                h0 = *(__half2*)&u2[j].x;
                h1 = *(__half2*)&u2[j].y;
            } else {
                h0 = __floats2half2_rn(f4[j].x, f4[j].y);
                h1 = __floats2half2_rn(f4[j].z, f4[j].w);
            }
            As[row * 20 + seg * 2]     = h0;
            As[row * 20 + seg * 2 + 1] = h1;
        }
    };
    auto stage_b = [&](int k0) {
#pragma unroll
        for (int j = 0; j < 4; j++) {
            int f  = tid + j * 256;     // 0..1023
            int k  = f >> 5;            // 0..31
            int cs = f & 31;            // col segment (4 cols)
            float4 v = *(const float4*)(B + (size_t)(k0 + k) * 128 + cs * 4);
            __half2 h0 = __floats2half2_rn(v.x, v.y);
            __half2 h1 = __floats2half2_rn(v.z, v.w);
            uint2 w;
            w.x = *(uint32_t*)&h0;
            w.y = *(uint32_t*)&h1;
            *(uint2*)&Bs[k * 136 + cs * 4] = w;  // 8B-aligned: 272B row stride
        }
    };

    // prologue
    load_a(0);
    store_a();
    stage_b(0);

    for (int k0 = 0; k0 < K; k0 += 32) {
        __syncthreads();               // tiles for k0 visible

        const bool has_next = (k0 + 32) < K;
        if (has_next) load_a(k0 + 32); // prefetch next A into regs

#pragma unroll
        for (int kc = 0; kc < 2; kc++) {
            const int kb = kc * 16;
            // b fragments: 4 n-tiles x 2 regs (each 2 halves along k)
            uint32_t bf[4][2];
#pragma unroll
            for (int nt = 0; nt < 4; nt++) {
                int col = wn * 32 + nt * 8 + g4;
                uint32_t lo0 = (uint32_t)__half_as_ushort(Bs[(kb + 2 * t4)     * 136 + col]);
                uint32_t hi0 = (uint32_t)__half_as_ushort(Bs[(kb + 2 * t4 + 1) * 136 + col]);
                uint32_t lo1 = (uint32_t)__half_as_ushort(Bs[(kb + 2 * t4 + 8) * 136 + col]);
                uint32_t hi1 = (uint32_t)__half_as_ushort(Bs[(kb + 2 * t4 + 9) * 136 + col]);
                bf[nt][0] = lo0 | (hi0 << 16);
                bf[nt][1] = lo1 | (hi1 << 16);
            }
            // a fragments: 4 m-tiles x 4 regs
            uint32_t af[4][4];
#pragma unroll
            for (int mt = 0; mt < 4; mt++) {
                int r = wm * 64 + mt * 16 + g4;
                int kh = kc * 8;       // half2 index base within row
                af[mt][0] = *(uint32_t*)&As[r * 20 + kh + t4];
                af[mt][1] = *(uint32_t*)&As[(r + 8) * 20 + kh + t4];
                af[mt][2] = *(uint32_t*)&As[r * 20 + kh + t4 + 4];
                af[mt][3] = *(uint32_t*)&As[(r + 8) * 20 + kh + t4 + 4];
            }
#pragma unroll
            for (int mt = 0; mt < 4; mt++)
#pragma unroll
                for (int nt = 0; nt < 4; nt++) {
                    asm volatile(
                        "mma.sync.aligned.m16n8k16.row.col.f32.f16.f16.f32 "
                        "{%0,%1,%2,%3}, {%4,%5,%6,%7}, {%8,%9}, {%0,%1,%2,%3};\n"
                        : "+f"(acc[mt][nt][0]), "+f"(acc[mt][nt][1]),
                          "+f"(acc[mt][nt][2]), "+f"(acc[mt][nt][3])
                        : "r"(af[mt][0]), "r"(af[mt][1]),
                          "r"(af[mt][2]), "r"(af[mt][3]),
                          "r"(bf[nt][0]), "r"(bf[nt][1]));
                }
        }
        __syncthreads();               // done reading k0 tiles

        if (has_next) {
            store_a();
            stage_b(k0 + 32);
        }
    }

    // ---- epilogue: bias (+ relu) + store (fp32 or fp16) ----
#pragma unroll
    for (int nt = 0; nt < 4; nt++) {
        int col = wn * 32 + nt * 8 + 2 * t4;
        float2 bv = *(const float2*)(bias + col);
#pragma unroll
        for (int mt = 0; mt < 4; mt++) {
            int r0 = m0 + wm * 64 + mt * 16 + g4;
            int r1 = r0 + 8;
            float v0 = acc[mt][nt][0] + bv.x;
            float v1 = acc[mt][nt][1] + bv.y;
            float v2 = acc[mt][nt][2] + bv.x;
            float v3 = acc[mt][nt][3] + bv.y;
            if (do_relu) {
                v0 = fmaxf(v0, 0.f); v1 = fmaxf(v1, 0.f);
                v2 = fmaxf(v2, 0.f); v3 = fmaxf(v3, 0.f);
            }
            if (Ch) {
                if (r0 < M) *(__half2*)(Ch + (size_t)r0 * 128 + col) =
                    __floats2half2_rn(v0, v1);
                if (r1 < M) *(__half2*)(Ch + (size_t)r1 * 128 + col) =
                    __floats2half2_rn(v2, v3);
            } else {
                if (r0 < M) *(float2*)(C + (size_t)r0 * 128 + col) = make_float2(v0, v1);
                if (r1 < M) *(float2*)(C + (size_t)r1 * 128 + col) = make_float2(v2, v3);
            }
        }
    }
}

// ---------------- launch -----------------------------------------------------
extern "C" void kernel_launch(void* const* d_in, const int* in_sizes, int n_in,
                              void* d_out, int out_size) {
    const float* node_feats  = (const float*)d_in[0];
    const float* edge_logits = (const float*)d_in[1];
    const float* W_proj      = (const float*)d_in[2];
    const float* b_proj      = (const float*)d_in[3];
    const float* W1          = (const float*)d_in[4];
    const float* b1          = (const float*)d_in[5];
    const float* W2          = (const float*)d_in[6];
    const float* b2          = (const float*)d_in[7];
    const int*   src         = (const int*)d_in[8];
    const int*   dst         = (const int*)d_in[9];
    float*       out         = (float*)d_out;

    void *p_hvh, *p_ctx, *p_h;
    cudaGetSymbolAddress(&p_hvh, g_hvh);
    cudaGetSymbolAddress(&p_ctx, g_ctx);
    cudaGetSymbolAddress(&p_h,   g_h);
    __half* hvh = (__half*)p_hvh;
    float*  ctx = (float*)p_ctx;
    __half* h   = (__half*)p_h;

    const int EB = (NE + 255) / 256;
    const int NB = (NN + 255) / 256;
    const int GB = (NN + 127) / 128;
    const int SB = (NN + 1023) / 1024;

    init_kernel<<<NB, 256>>>();
    count_pass<<<EB, 256>>>(dst);

    scan_phase_a<<<SB, 1024>>>();
    scan_phase_b<<<1, 128>>>(SB);
    scan_phase_c<<<NB, 256>>>();

    edge_scatter<<<EB, 256>>>(edge_logits, src, dst);

    // hv(fp16) = node_feats @ W_proj + b_proj (no relu)
    gemm_f16<<<GB, 256>>>(node_feats, node_feats, W_proj, b_proj,
                          nullptr, hvh, NN, 128, 0, 0);

    // ctx = elu( (segment_sum(e * hv[src], dst)) / z )
    aggregate_kernel<<<(NN * 32 + 255) / 256, 256>>>((const __half2*)hvh, ctx);

    // h(fp16) = relu([ctx, node_feats] @ W1 + b1)   (K = 256)
    gemm_f16<<<GB, 256>>>(ctx, node_feats, W1, b1, nullptr, h, NN, 256, 1, 0);

    // out = relu(h @ W2 + b2)   (A is fp16)
    gemm_f16<<<GB, 256>>>(h, h, W2, b2, out, nullptr, NN, 128, 1, 1);
}

// round 9
// speedup vs baseline: 1.2622x; 1.2622x over previous
#include <cuda_runtime.h>
#include <cuda_fp16.h>
#include <math.h>
#include <stdint.h>

#define NN 100000
#define NE 1600000
#define DIM 128

// ---------------- scratch (static device globals; no allocation) -------------
__device__ int    g_count[NN];                  // in-degree histogram
__device__ int    g_off[NN + 1];                // CSR offsets
__device__ int    g_cur[NN];                    // scatter cursors
__device__ int2   g_edge[NE];                   // packed (src, exp-bits) sorted by dst
__device__ __half g_hvh[(size_t)NN * DIM];      // projected node feats (fp16)
__device__ float  g_ctx[(size_t)NN * DIM];      // aggregated context (fp32)
__device__ float  g_h[(size_t)NN * DIM];        // hidden layer (fp32)
// scan scratch
__device__ int    g_excl[NN];
__device__ int    g_bsum[128];
__device__ int    g_bpre[128];

// ---------------- small kernels ---------------------------------------------
__global__ void init_kernel() {
    int i = blockIdx.x * blockDim.x + threadIdx.x;
    if (i < NN) g_count[i] = 0;
}

// count-only pass (z is accumulated inside the aggregate)
__global__ void count_pass(const int* __restrict__ dst) {
    int i = blockIdx.x * blockDim.x + threadIdx.x;
    if (i < NE) atomicAdd(&g_count[dst[i]], 1);
}

// ---------------- 3-phase parallel scan of g_count -> g_off ------------------
__global__ void scan_phase_a() {
    __shared__ int sh[1024];
    int t = threadIdx.x;
    int b = blockIdx.x;
    int i = b * 1024 + t;
    int c = (i < NN) ? g_count[i] : 0;
    sh[t] = c;
    __syncthreads();
#pragma unroll
    for (int off = 1; off < 1024; off <<= 1) {
        int v = sh[t] + ((t >= off) ? sh[t - off] : 0);
        __syncthreads();
        sh[t] = v;
        __syncthreads();
    }
    if (i < NN) g_excl[i] = sh[t] - c;
    if (t == 1023) g_bsum[b] = sh[1023];
}

__global__ void scan_phase_b(int nb) {
    __shared__ int sh[128];
    int t = threadIdx.x;
    int v0 = (t < nb) ? g_bsum[t] : 0;
    sh[t] = v0;
    __syncthreads();
#pragma unroll
    for (int off = 1; off < 128; off <<= 1) {
        int v = sh[t] + ((t >= off) ? sh[t - off] : 0);
        __syncthreads();
        sh[t] = v;
        __syncthreads();
    }
    if (t < nb) g_bpre[t] = sh[t] - v0;
    if (t == nb - 1) g_off[NN] = sh[t];
}

__global__ void scan_phase_c() {
    int i = blockIdx.x * blockDim.x + threadIdx.x;
    if (i < NN) {
        int o = g_bpre[i >> 10] + g_excl[i];
        g_off[i] = o;
        g_cur[i] = o;
    }
}

// scatter (src, unnormalized e=exp(logit)) into CSR order.
// (no max-shift needed: logits ~ N(0,1); exp cannot overflow and the
//  normalized ratio e/z is shift-invariant up to fp32 rounding)
__global__ void edge_scatter(const float* __restrict__ logits,
                             const int* __restrict__ src,
                             const int* __restrict__ dst) {
    int i = blockIdx.x * blockDim.x + threadIdx.x;
    if (i < NE) {
        int d = dst[i];
        int pos = atomicAdd(&g_cur[d], 1);
        float e = expf(logits[i]);
        g_edge[pos] = make_int2(src[i], __float_as_int(e));
    }
}

// warp per destination node: ctx[v] = elu( (sum_e e_uv * hv[u]) / (sum_e e_uv) )
// hv fp16, fp32 accumulate; z accumulated in-loop (lane-redundant, free).
__global__ void aggregate_kernel(const __half2* __restrict__ hv2,
                                 float* __restrict__ ctx) {
    int gw   = (blockIdx.x * blockDim.x + threadIdx.x) >> 5;
    int lane = threadIdx.x & 31;
    if (gw >= NN) return;
    int s = g_off[gw];
    int e = g_off[gw + 1];
    float4 acc = make_float4(0.f, 0.f, 0.f, 0.f);
    float az = 0.f;
    for (int i = s; i < e; i++) {
        int2  ed = g_edge[i];
        float a  = __int_as_float(ed.y);
        az += a;
        const __half2* row = hv2 + (size_t)ed.x * (DIM / 2) + lane * 2;
        uint2 u = *(const uint2*)row;
        __half2 h0 = *(__half2*)&u.x;
        __half2 h1 = *(__half2*)&u.y;
        float2 f0 = __half22float2(h0);
        float2 f1 = __half22float2(h1);
        acc.x = fmaf(a, f0.x, acc.x);
        acc.y = fmaf(a, f0.y, acc.y);
        acc.z = fmaf(a, f1.x, acc.z);
        acc.w = fmaf(a, f1.y, acc.w);
    }
    if (e > s) {
        float invz = 1.0f / az;
        acc.x *= invz; acc.y *= invz; acc.z *= invz; acc.w *= invz;
    }
    acc.x = acc.x > 0.f ? acc.x : expm1f(acc.x);
    acc.y = acc.y > 0.f ? acc.y : expm1f(acc.y);
    acc.z = acc.z > 0.f ? acc.z : expm1f(acc.z);
    acc.w = acc.w > 0.f ? acc.w : expm1f(acc.w);
    *(float4*)(ctx + (size_t)gw * DIM + lane * 4) = acc;
}

// ---------------- tf32 tensor-core GEMM (A-prefetch pipelined) ---------------
// C[M,128] = act( A1[:,0:128] @ B[0:128,:] (+ A2[:,0:128] @ B[128:256,:]) + bias )
// Optional fp16 output (Ch != nullptr) for the projection GEMM.
//   As[row][36]: bank = (4*row + k) % 32 -> conflict-free a-frag loads.
//   Bs[k][136]:  bank = (8*k + n) % 32  -> conflict-free b-frag loads.

__device__ __forceinline__ uint32_t f2tf32(float x) {
    uint32_t u;
    asm("cvt.rna.tf32.f32 %0, %1;" : "=r"(u) : "f"(x));
    return u;
}

__device__ __forceinline__ void load_a_tile(const float* __restrict__ A1,
                                            const float* __restrict__ A2,
                                            int m0, int k0, int M, int tid,
                                            float4 r[4]) {
#pragma unroll
    for (int j = 0; j < 4; j++) {
        int f   = tid + j * 256;        // 0..1023
        int row = f >> 3;               // 0..127
        int seg = f & 7;                // 0..7
        int g   = m0 + row;
        int kc  = k0 + seg * 4;
        const float* Ap = A1;
        if (kc >= 128) { Ap = A2; kc -= 128; }
        float4 v = make_float4(0.f, 0.f, 0.f, 0.f);
        if (g < M) v = *(const float4*)(Ap + (size_t)g * 128 + kc);
        r[j] = v;
    }
}

__device__ __forceinline__ void store_a_tile(uint32_t* As, int tid,
                                             const float4 r[4]) {
#pragma unroll
    for (int j = 0; j < 4; j++) {
        int f   = tid + j * 256;
        int row = f >> 3;
        int seg = f & 7;
        uint4 u;
        u.x = f2tf32(r[j].x); u.y = f2tf32(r[j].y);
        u.z = f2tf32(r[j].z); u.w = f2tf32(r[j].w);
        *(uint4*)&As[row * 36 + seg * 4] = u;
    }
}

__device__ __forceinline__ void stage_b_tile(uint32_t* Bs,
                                             const float* __restrict__ B,
                                             int k0, int tid) {
#pragma unroll
    for (int j = 0; j < 4; j++) {
        int f  = tid + j * 256;         // 0..1023
        int k  = f >> 5;                // 0..31
        int cs = f & 31;                // 0..31
        float4 v = *(const float4*)(B + (size_t)(k0 + k) * 128 + cs * 4);
        uint4 u;
        u.x = f2tf32(v.x); u.y = f2tf32(v.y);
        u.z = f2tf32(v.z); u.w = f2tf32(v.w);
        *(uint4*)&Bs[k * 136 + cs * 4] = u;
    }
}

__global__ void __launch_bounds__(256, 2)
gemm_tf32(const float* __restrict__ A1, const float* __restrict__ A2,
          const float* __restrict__ B, const float* __restrict__ bias,
          float* __restrict__ C, __half* __restrict__ Ch,
          int M, int K, int do_relu) {
    __shared__ uint32_t As[128 * 36];
    __shared__ uint32_t Bs[32 * 136];

    const int tid  = threadIdx.x;
    const int lane = tid & 31;
    const int wid  = tid >> 5;
    const int wm   = wid >> 2;        // 0..1  -> warp rows base wm*64
    const int wn   = wid & 3;         // 0..3  -> warp cols base wn*32
    const int m0   = blockIdx.x * 128;
    const int g4   = lane >> 2;       // groupID
    const int t4   = lane & 3;        // thread-in-group

    float acc[4][4][4];
#pragma unroll
    for (int mt = 0; mt < 4; mt++)
#pragma unroll
        for (int nt = 0; nt < 4; nt++)
#pragma unroll
            for (int r = 0; r < 4; r++) acc[mt][nt][r] = 0.f;

    // prologue: stage first tiles
    float4 ra[4];
    load_a_tile(A1, A2, m0, 0, M, tid, ra);
    store_a_tile(As, tid, ra);
    stage_b_tile(Bs, B, 0, tid);

    for (int k0 = 0; k0 < K; k0 += 32) {
        __syncthreads();               // tiles for k0 visible

        const bool has_next = (k0 + 32) < K;
        if (has_next)                  // prefetch next A into regs
            load_a_tile(A1, A2, m0, k0 + 32, M, tid, ra);

#pragma unroll
        for (int kc = 0; kc < 4; kc++) {
            const int kb = kc * 8;
            uint32_t bf[4][2];
#pragma unroll
            for (int nt = 0; nt < 4; nt++) {
                int col = wn * 32 + nt * 8 + g4;
                bf[nt][0] = Bs[(kb + t4) * 136 + col];
                bf[nt][1] = Bs[(kb + t4 + 4) * 136 + col];
            }
            uint32_t af[4][4];
#pragma unroll
            for (int mt = 0; mt < 4; mt++) {
                int r = wm * 64 + mt * 16 + g4;
                af[mt][0] = As[r * 36 + kb + t4];
                af[mt][1] = As[(r + 8) * 36 + kb + t4];
                af[mt][2] = As[r * 36 + kb + t4 + 4];
                af[mt][3] = As[(r + 8) * 36 + kb + t4 + 4];
            }
#pragma unroll
            for (int mt = 0; mt < 4; mt++)
#pragma unroll
                for (int nt = 0; nt < 4; nt++) {
                    asm volatile(
                        "mma.sync.aligned.m16n8k8.row.col.f32.tf32.tf32.f32 "
                        "{%0,%1,%2,%3}, {%4,%5,%6,%7}, {%8,%9}, {%0,%1,%2,%3};\n"
                        : "+f"(acc[mt][nt][0]), "+f"(acc[mt][nt][1]),
                          "+f"(acc[mt][nt][2]), "+f"(acc[mt][nt][3])
                        : "r"(af[mt][0]), "r"(af[mt][1]),
                          "r"(af[mt][2]), "r"(af[mt][3]),
                          "r"(bf[nt][0]), "r"(bf[nt][1]));
                }
        }
        __syncthreads();               // done reading k0 tiles

        if (has_next) {
            store_a_tile(As, tid, ra);
            stage_b_tile(Bs, B, k0 + 32, tid);
        }
    }

    // ---- epilogue: bias (+ relu) + store (fp32 or fp16) ----
#pragma unroll
    for (int nt = 0; nt < 4; nt++) {
        int col = wn * 32 + nt * 8 + 2 * t4;
        float2 bv = *(const float2*)(bias + col);
#pragma unroll
        for (int mt = 0; mt < 4; mt++) {
            int r0 = m0 + wm * 64 + mt * 16 + g4;
            int r1 = r0 + 8;
            float v0 = acc[mt][nt][0] + bv.x;
            float v1 = acc[mt][nt][1] + bv.y;
            float v2 = acc[mt][nt][2] + bv.x;
            float v3 = acc[mt][nt][3] + bv.y;
            if (do_relu) {
                v0 = fmaxf(v0, 0.f); v1 = fmaxf(v1, 0.f);
                v2 = fmaxf(v2, 0.f); v3 = fmaxf(v3, 0.f);
            }
            if (Ch) {
                if (r0 < M) *(__half2*)(Ch + (size_t)r0 * 128 + col) =
                    __floats2half2_rn(v0, v1);
                if (r1 < M) *(__half2*)(Ch + (size_t)r1 * 128 + col) =
                    __floats2half2_rn(v2, v3);
            } else {
                if (r0 < M) *(float2*)(C + (size_t)r0 * 128 + col) = make_float2(v0, v1);
                if (r1 < M) *(float2*)(C + (size_t)r1 * 128 + col) = make_float2(v2, v3);
            }
        }
    }
}

// ---------------- launch -----------------------------------------------------
extern "C" void kernel_launch(void* const* d_in, const int* in_sizes, int n_in,
                              void* d_out, int out_size) {
    const float* node_feats  = (const float*)d_in[0];
    const float* edge_logits = (const float*)d_in[1];
    const float* W_proj      = (const float*)d_in[2];
    const float* b_proj      = (const float*)d_in[3];
    const float* W1          = (const float*)d_in[4];
    const float* b1          = (const float*)d_in[5];
    const float* W2          = (const float*)d_in[6];
    const float* b2          = (const float*)d_in[7];
    const int*   src         = (const int*)d_in[8];
    const int*   dst         = (const int*)d_in[9];
    float*       out         = (float*)d_out;

    void *p_hvh, *p_ctx, *p_h;
    cudaGetSymbolAddress(&p_hvh, g_hvh);
    cudaGetSymbolAddress(&p_ctx, g_ctx);
    cudaGetSymbolAddress(&p_h,   g_h);
    __half* hvh = (__half*)p_hvh;
    float*  ctx = (float*)p_ctx;
    float*  h   = (float*)p_h;

    const int EB = (NE + 255) / 256;
    const int NB = (NN + 255) / 256;
    const int GB = (NN + 127) / 128;
    const int SB = (NN + 1023) / 1024;

    init_kernel<<<NB, 256>>>();
    count_pass<<<EB, 256>>>(dst);

    scan_phase_a<<<SB, 1024>>>();
    scan_phase_b<<<1, 128>>>(SB);
    scan_phase_c<<<NB, 256>>>();

    edge_scatter<<<EB, 256>>>(edge_logits, src, dst);

    // hv(fp16) = node_feats @ W_proj + b_proj (no relu)
    gemm_tf32<<<GB, 256>>>(node_feats, node_feats, W_proj, b_proj,
                           nullptr, hvh, NN, 128, 0);

    // ctx = elu( (segment_sum(e * hv[src], dst)) / z )
    aggregate_kernel<<<(NN * 32 + 255) / 256, 256>>>((const __half2*)hvh, ctx);

    // h = relu([ctx, node_feats] @ W1 + b1)   (K = 256)
    gemm_tf32<<<GB, 256>>>(ctx, node_feats, W1, b1, h, nullptr, NN, 256, 1);

    // out = relu(h @ W2 + b2)
    gemm_tf32<<<GB, 256>>>(h, h, W2, b2, out, nullptr, NN, 128, 1);
}

// round 13
// speedup vs baseline: 1.4047x; 1.1129x over previous
#include <cuda_runtime.h>
#include <cuda_fp16.h>
#include <math.h>
#include <stdint.h>

#define NN 100000
#define NE 1600000
#define DIM 128

// ---------------- scratch (static device globals; no allocation) -------------
__device__ int    g_count[NN];                  // in-degree histogram
__device__ int    g_off[NN + 1];                // CSR offsets
__device__ int    g_cur[NN];                    // scatter cursors
__device__ int2   g_edge[NE];                   // packed (src, exp-bits) sorted by dst
__device__ __half g_hvh[(size_t)NN * DIM];      // projected node feats (fp16)
__device__ float  g_ctx[(size_t)NN * DIM];      // aggregated context (fp32)
__device__ __half g_h[(size_t)NN * DIM];        // hidden layer (fp16)
// scan scratch
__device__ int    g_excl[NN];
__device__ int    g_bsum[128];
__device__ int    g_bpre[128];

// ---------------- small kernels ---------------------------------------------
__global__ void init_kernel() {
    int i = blockIdx.x * blockDim.x + threadIdx.x;
    if (i < NN) g_count[i] = 0;
}

// count-only pass (z is accumulated inside the aggregate)
__global__ void count_pass(const int* __restrict__ dst) {
    int i = blockIdx.x * blockDim.x + threadIdx.x;
    if (i < NE) atomicAdd(&g_count[dst[i]], 1);
}

// ---------------- 3-phase parallel scan of g_count -> g_off ------------------
__global__ void scan_phase_a() {
    __shared__ int sh[1024];
    int t = threadIdx.x;
    int b = blockIdx.x;
    int i = b * 1024 + t;
    int c = (i < NN) ? g_count[i] : 0;
    sh[t] = c;
    __syncthreads();
#pragma unroll
    for (int off = 1; off < 1024; off <<= 1) {
        int v = sh[t] + ((t >= off) ? sh[t - off] : 0);
        __syncthreads();
        sh[t] = v;
        __syncthreads();
    }
    if (i < NN) g_excl[i] = sh[t] - c;
    if (t == 1023) g_bsum[b] = sh[1023];
}

__global__ void scan_phase_b(int nb) {
    __shared__ int sh[128];
    int t = threadIdx.x;
    int v0 = (t < nb) ? g_bsum[t] : 0;
    sh[t] = v0;
    __syncthreads();
#pragma unroll
    for (int off = 1; off < 128; off <<= 1) {
        int v = sh[t] + ((t >= off) ? sh[t - off] : 0);
        __syncthreads();
        sh[t] = v;
        __syncthreads();
    }
    if (t < nb) g_bpre[t] = sh[t] - v0;
    if (t == nb - 1) g_off[NN] = sh[t];
}

__global__ void scan_phase_c() {
    int i = blockIdx.x * blockDim.x + threadIdx.x;
    if (i < NN) {
        int o = g_bpre[i >> 10] + g_excl[i];
        g_off[i] = o;
        g_cur[i] = o;
    }
}

// scatter (src, unnormalized e=exp(logit)) into CSR order.
// (no max-shift needed: logits ~ N(0,1); exp cannot overflow and the
//  normalized ratio e/z is shift-invariant up to fp32 rounding)
__global__ void edge_scatter(const float* __restrict__ logits,
                             const int* __restrict__ src,
                             const int* __restrict__ dst) {
    int i = blockIdx.x * blockDim.x + threadIdx.x;
    if (i < NE) {
        int d = dst[i];
        int pos = atomicAdd(&g_cur[d], 1);
        float e = expf(logits[i]);
        g_edge[pos] = make_int2(src[i], __float_as_int(e));
    }
}

// warp per destination node: ctx[v] = elu( (sum_e e_uv * hv[u]) / (sum_e e_uv) )
__global__ void aggregate_kernel(const __half2* __restrict__ hv2,
                                 float* __restrict__ ctx) {
    int gw   = (blockIdx.x * blockDim.x + threadIdx.x) >> 5;
    int lane = threadIdx.x & 31;
    if (gw >= NN) return;
    int s = g_off[gw];
    int e = g_off[gw + 1];
    float4 acc = make_float4(0.f, 0.f, 0.f, 0.f);
    float az = 0.f;
    for (int i = s; i < e; i++) {
        int2  ed = g_edge[i];
        float a  = __int_as_float(ed.y);
        az += a;
        const __half2* row = hv2 + (size_t)ed.x * (DIM / 2) + lane * 2;
        uint2 u = *(const uint2*)row;
        __half2 h0 = *(__half2*)&u.x;
        __half2 h1 = *(__half2*)&u.y;
        float2 f0 = __half22float2(h0);
        float2 f1 = __half22float2(h1);
        acc.x = fmaf(a, f0.x, acc.x);
        acc.y = fmaf(a, f0.y, acc.y);
        acc.z = fmaf(a, f1.x, acc.z);
        acc.w = fmaf(a, f1.y, acc.w);
    }
    if (e > s) {
        float invz = 1.0f / az;
        acc.x *= invz; acc.y *= invz; acc.z *= invz; acc.w *= invz;
    }
    acc.x = acc.x > 0.f ? acc.x : expm1f(acc.x);
    acc.y = acc.y > 0.f ? acc.y : expm1f(acc.y);
    acc.z = acc.z > 0.f ? acc.z : expm1f(acc.z);
    acc.w = acc.w > 0.f ? acc.w : expm1f(acc.w);
    *(float4*)(ctx + (size_t)gw * DIM + lane * 4) = acc;
}

// ---------------- fp16 tensor-core GEMM (A-prefetch pipelined) ---------------
// C[M,128] = act( A1[:,0:128] @ B[0:128,:] (+ A2[:,0:128] @ B[128:256,:]) + bias )
// mma.sync.aligned.m16n8k16.row.col.f32.f16.f16.f32; fp32 accumulate.
// 128x128 block tile, 8 warps (2x4), warp tile 64x32, BK=32 (2 k16 steps).
//
// A staged as half2 [row][k2], row stride 20 words:
//   a-frag word = row*20 + t4(+4); bank = (4*g4 + t4) mod 32 -> 32 distinct
//   banks across the warp -> conflict-free, single 32-bit LDS per frag reg.
// B staged as half2 k-pairs [k2][col], row stride 136 words:
//   word = k2*136 + col; t4 -> {0,8,16,24} bank offset, g4 -> {0..7}
//   -> 32 distinct banks -> conflict-free, single 32-bit LDS per frag reg.
//   (This fixes R8's scalar-u16 B staging, which was the regression.)
// Templated on A_HALF so each instantiation carries only its staging path.

template <int A_HALF>
__global__ void __launch_bounds__(256, 2)
gemm_f16(const void* __restrict__ A1v, const void* __restrict__ A2v,
         const float* __restrict__ B, const float* __restrict__ bias,
         float* __restrict__ C, __half* __restrict__ Ch,
         int M, int K, int do_relu) {
    __shared__ __half2 As[128 * 20];   // [row][k2], stride 20
    __shared__ __half2 Bs[16 * 136];   // [k2][col], stride 136

    const int tid  = threadIdx.x;
    const int lane = tid & 31;
    const int wid  = tid >> 5;
    const int wm   = wid >> 2;        // 0..1  -> warp rows base wm*64
    const int wn   = wid & 3;         // 0..3  -> warp cols base wn*32
    const int m0   = blockIdx.x * 128;
    const int g4   = lane >> 2;       // groupID
    const int t4   = lane & 3;        // thread-in-group

    const float*  A1f = (const float*)A1v;
    const float*  A2f = (const float*)A2v;
    const __half* A1h = (const __half*)A1v;

    float acc[4][4][4];
#pragma unroll
    for (int mt = 0; mt < 4; mt++)
#pragma unroll
        for (int nt = 0; nt < 4; nt++)
#pragma unroll
            for (int r = 0; r < 4; r++) acc[mt][nt][r] = 0.f;

    // A register prefetch buffers (fp32 path: float4; fp16 path: uint2)
    float4 f4[4];
    uint2  u2[4];

    auto load_a = [&](int k0) {
#pragma unroll
        for (int j = 0; j < 4; j++) {
            int f   = tid + j * 256;    // 0..1023
            int row = f >> 3;           // 0..127
            int seg = f & 7;            // 0..7 (4 k-values each)
            int g   = m0 + row;
            int kc  = k0 + seg * 4;
            if (A_HALF) {
                uint2 v = make_uint2(0u, 0u);
                if (g < M) v = *(const uint2*)(A1h + (size_t)g * 128 + kc);
                u2[j] = v;
            } else {
                const float* Ap = A1f;
                if (kc >= 128) { Ap = A2f; kc -= 128; }
                float4 v = make_float4(0.f, 0.f, 0.f, 0.f);
                if (g < M) v = *(const float4*)(Ap + (size_t)g * 128 + kc);
                f4[j] = v;
            }
        }
    };
    auto store_a = [&]() {
#pragma unroll
        for (int j = 0; j < 4; j++) {
            int f   = tid + j * 256;
            int row = f >> 3;
            int seg = f & 7;
            __half2 h0, h1;
            if (A_HALF) {
                h0 = *(__half2*)&u2[j].x;
                h1 = *(__half2*)&u2[j].y;
            } else {
                h0 = __floats2half2_rn(f4[j].x, f4[j].y);
                h1 = __floats2half2_rn(f4[j].z, f4[j].w);
            }
            As[row * 20 + seg * 2]     = h0;   // 8B store (contiguous pair)
            As[row * 20 + seg * 2 + 1] = h1;
        }
    };
    // B: thread loads rows 2*k2 and 2*k2+1 (4 cols each), transposes into
    // 4 half2 k-pair words, stores 16B at [k2][cs*4].
    auto stage_b = [&](int k0) {
#pragma unroll
        for (int j = 0; j < 2; j++) {
            int f  = tid + j * 256;     // 0..511
            int k2 = f >> 5;            // 0..15
            int cs = f & 31;            // col segment (4 cols)
            const float* r0 = B + (size_t)(k0 + 2 * k2) * 128 + cs * 4;
            float4 va = *(const float4*)r0;
            float4 vb = *(const float4*)(r0 + 128);
            __half2 w0 = __floats2half2_rn(va.x, vb.x);
            __half2 w1 = __floats2half2_rn(va.y, vb.y);
            __half2 w2 = __floats2half2_rn(va.z, vb.z);
            __half2 w3 = __floats2half2_rn(va.w, vb.w);
            uint4 u;
            u.x = *(uint32_t*)&w0; u.y = *(uint32_t*)&w1;
            u.z = *(uint32_t*)&w2; u.w = *(uint32_t*)&w3;
            *(uint4*)&Bs[k2 * 136 + cs * 4] = u;
        }
    };

    // prologue
    load_a(0);
    store_a();
    stage_b(0);

    const uint32_t* As32 = (const uint32_t*)As;
    const uint32_t* Bs32 = (const uint32_t*)Bs;

    for (int k0 = 0; k0 < K; k0 += 32) {
        __syncthreads();               // tiles for k0 visible

        const bool has_next = (k0 + 32) < K;
        if (has_next) load_a(k0 + 32); // prefetch next A into regs

#pragma unroll
        for (int kc = 0; kc < 2; kc++) {
            const int kh = kc * 8;     // half2 k-index base
            uint32_t bf[4][2];
#pragma unroll
            for (int nt = 0; nt < 4; nt++) {
                int col = wn * 32 + nt * 8 + g4;
                bf[nt][0] = Bs32[(kh + t4) * 136 + col];
                bf[nt][1] = Bs32[(kh + t4 + 4) * 136 + col];
            }
            uint32_t af[4][4];
#pragma unroll
            for (int mt = 0; mt < 4; mt++) {
                int r = wm * 64 + mt * 16 + g4;
                af[mt][0] = As32[r * 20 + kh + t4];
                af[mt][1] = As32[(r + 8) * 20 + kh + t4];
                af[mt][2] = As32[r * 20 + kh + t4 + 4];
                af[mt][3] = As32[(r + 8) * 20 + kh + t4 + 4];
            }
#pragma unroll
            for (int mt = 0; mt < 4; mt++)
#pragma unroll
                for (int nt = 0; nt < 4; nt++) {
                    asm volatile(
                        "mma.sync.aligned.m16n8k16.row.col.f32.f16.f16.f32 "
                        "{%0,%1,%2,%3}, {%4,%5,%6,%7}, {%8,%9}, {%0,%1,%2,%3};\n"
                        : "+f"(acc[mt][nt][0]), "+f"(acc[mt][nt][1]),
                          "+f"(acc[mt][nt][2]), "+f"(acc[mt][nt][3])
                        : "r"(af[mt][0]), "r"(af[mt][1]),
                          "r"(af[mt][2]), "r"(af[mt][3]),
                          "r"(bf[nt][0]), "r"(bf[nt][1]));
                }
        }
        __syncthreads();               // done reading k0 tiles

        if (has_next) {
            store_a();
            stage_b(k0 + 32);
        }
    }

    // ---- epilogue: bias (+ relu) + store (fp32 or fp16) ----
#pragma unroll
    for (int nt = 0; nt < 4; nt++) {
        int col = wn * 32 + nt * 8 + 2 * t4;
        float2 bv = *(const float2*)(bias + col);
#pragma unroll
        for (int mt = 0; mt < 4; mt++) {
            int r0 = m0 + wm * 64 + mt * 16 + g4;
            int r1 = r0 + 8;
            float v0 = acc[mt][nt][0] + bv.x;
            float v1 = acc[mt][nt][1] + bv.y;
            float v2 = acc[mt][nt][2] + bv.x;
            float v3 = acc[mt][nt][3] + bv.y;
            if (do_relu) {
                v0 = fmaxf(v0, 0.f); v1 = fmaxf(v1, 0.f);
                v2 = fmaxf(v2, 0.f); v3 = fmaxf(v3, 0.f);
            }
            if (Ch) {
                if (r0 < M) *(__half2*)(Ch + (size_t)r0 * 128 + col) =
                    __floats2half2_rn(v0, v1);
                if (r1 < M) *(__half2*)(Ch + (size_t)r1 * 128 + col) =
                    __floats2half2_rn(v2, v3);
            } else {
                if (r0 < M) *(float2*)(C + (size_t)r0 * 128 + col) = make_float2(v0, v1);
                if (r1 < M) *(float2*)(C + (size_t)r1 * 128 + col) = make_float2(v2, v3);
            }
        }
    }
}

// ---------------- launch -----------------------------------------------------
extern "C" void kernel_launch(void* const* d_in, const int* in_sizes, int n_in,
                              void* d_out, int out_size) {
    const float* node_feats  = (const float*)d_in[0];
    const float* edge_logits = (const float*)d_in[1];
    const float* W_proj      = (const float*)d_in[2];
    const float* b_proj      = (const float*)d_in[3];
    const float* W1          = (const float*)d_in[4];
    const float* b1          = (const float*)d_in[5];
    const float* W2          = (const float*)d_in[6];
    const float* b2          = (const float*)d_in[7];
    const int*   src         = (const int*)d_in[8];
    const int*   dst         = (const int*)d_in[9];
    float*       out         = (float*)d_out;

    void *p_hvh, *p_ctx, *p_h;
    cudaGetSymbolAddress(&p_hvh, g_hvh);
    cudaGetSymbolAddress(&p_ctx, g_ctx);
    cudaGetSymbolAddress(&p_h,   g_h);
    __half* hvh = (__half*)p_hvh;
    float*  ctx = (float*)p_ctx;
    __half* h   = (__half*)p_h;

    const int EB = (NE + 255) / 256;
    const int NB = (NN + 255) / 256;
    const int GB = (NN + 127) / 128;
    const int SB = (NN + 1023) / 1024;

    init_kernel<<<NB, 256>>>();
    count_pass<<<EB, 256>>>(dst);

    scan_phase_a<<<SB, 1024>>>();
    scan_phase_b<<<1, 128>>>(SB);
    scan_phase_c<<<NB, 256>>>();

    edge_scatter<<<EB, 256>>>(edge_logits, src, dst);

    // hv(fp16) = node_feats @ W_proj + b_proj (no relu)
    gemm_f16<0><<<GB, 256>>>(node_feats, node_feats, W_proj, b_proj,
                             nullptr, hvh, NN, 128, 0);

    // ctx = elu( (segment_sum(e * hv[src], dst)) / z )
    aggregate_kernel<<<(NN * 32 + 255) / 256, 256>>>((const __half2*)hvh, ctx);

    // h(fp16) = relu([ctx, node_feats] @ W1 + b1)   (K = 256)
    gemm_f16<0><<<GB, 256>>>(ctx, node_feats, W1, b1, nullptr, h, NN, 256, 1);

    // out = relu(h @ W2 + b2)   (A is fp16)
    gemm_f16<1><<<GB, 256>>>(h, h, W2, b2, out, nullptr, NN, 128, 1);
}